// round 17
// baseline (speedup 1.0000x reference)
#include <cuda_runtime.h>
#include <cuda_bf16.h>
#include <cstdint>

#define N_NODES 100000
#define N_EDGES 1600000
#define D 64
#define ELL_W 64     // slots per node; P(Poisson(16) >= 64) ~ 1e-19
#define NH 50000     // node half

// ---------------- scratch (static device globals; no allocation) ----------------
__device__ __align__(16) float  g_t0[(size_t)N_NODES * D];  // feature ping
__device__ __align__(16) float  g_t1[(size_t)N_NODES * D];  // feature pong
__device__ __align__(16) float  g_agg[(size_t)N_NODES * D]; // aggregation output
__device__ __align__(16) int    g_ell[(size_t)N_NODES * ELL_W];
__device__ __align__(16) int    g_cnt[N_NODES];             // in-degree / fill cursor
__device__ __align__(16) float  g_deg[N_NODES];             // out-degree count (float)
__device__ __align__(16) float  g_dinv[N_NODES];            // 1/max(deg,1)
__device__ __align__(16) float  g_msum[D];
__device__ int g_is64;

// ---------------- f32x2 helpers -----------------------------------------------------
#define FMA2(d, a, b) \
    asm("fma.rn.f32x2 %0, %1, %2, %0;" : "+l"(d) : "l"(a), "l"(b))

__device__ __forceinline__ uint64_t pack2(float x) {
    uint64_t p;
    asm("mov.b64 %0, {%1, %1};" : "=l"(p) : "f"(x));
    return p;
}
__device__ __forceinline__ float lo32(uint64_t v) {
    return __uint_as_float((unsigned)v);
}
__device__ __forceinline__ float hi32(uint64_t v) {
    return __uint_as_float((unsigned)(v >> 32));
}

// ---------------- detect: 256 parallel loads decide int64 vs int32 ------------------
__global__ void gcn_detect(const void* __restrict__ src) {
    __shared__ int ok;
    if (threadIdx.x == 0) ok = 1;
    __syncthreads();
    long long v = ((const long long*)src)[threadIdx.x];
    if (v < 0 || v >= N_NODES) ok = 0;     // benign race, all writers write 0
    __syncthreads();
    if (threadIdx.x == 0) g_is64 = ok;     // JAX int64 silently -> int32
}

// ---------------- build: single-pass ELL + out-degree histogram; 4 edges/thread ------
__global__ void gcn_build(const void* __restrict__ src, const void* __restrict__ dst) {
    int q = blockIdx.x * blockDim.x + threadIdx.x;
    int e0 = q * 4;
    if (e0 >= N_EDGES) return;
    const int is64 = g_is64;
    int s[4], d[4];
    if (!is64) {
        int4 sv = __ldg((const int4*)src + q);
        int4 dv = __ldg((const int4*)dst + q);
        s[0]=sv.x; s[1]=sv.y; s[2]=sv.z; s[3]=sv.w;
        d[0]=dv.x; d[1]=dv.y; d[2]=dv.z; d[3]=dv.w;
    } else {
        #pragma unroll
        for (int i = 0; i < 4; i++) {
            s[i] = (int)((const long long*)src)[e0 + i];
            d[i] = (int)((const long long*)dst)[e0 + i];
        }
    }
    #pragma unroll
    for (int i = 0; i < 4; i++) {
        int ss = ((unsigned)s[i] < N_NODES) ? s[i] : 0;
        int dd = ((unsigned)d[i] < N_NODES) ? d[i] : 0;
        atomicAdd(&g_deg[ss], 1.0f);
        int pos = atomicAdd(&g_cnt[dd], 1);
        if (pos < ELL_W) g_ell[(size_t)dd * ELL_W + pos] = ss;
    }
}

// ---------------- deginv: g_dinv = 1/max(deg,1) ----------------------------------------
__global__ void gcn_deginv() {
    int i = blockIdx.x * blockDim.x + threadIdx.x;
    if (i < N_NODES) g_dinv[i] = __fdividef(1.0f, fmaxf(g_deg[i], 1.0f));
}

// ---------------- fused prologue + GEMM over node range [base, end) --------------------
// t_out[n,:] = prologue(in[n,:]) @ W
// prologue(x) = (use_relu ? relu(x+bias) : x) * (use_deg ? dinv[n] : 1)
__global__ __launch_bounds__(128) void gcn_gemm(
    const float* __restrict__ in, const float* __restrict__ W,
    const float* __restrict__ bias, float* __restrict__ t_out,
    int use_relu, int use_deg, int base, int end)
{
    __shared__ float Ws[D][D];        // 16 KB
    __shared__ float Xs[128][68];     // 34.8 KB

    const int tid = threadIdx.x;
    const int n0  = base + blockIdx.x * 128;

    {
        const float4* w4 = (const float4*)W;
        float4* ws4 = (float4*)&Ws[0][0];
        #pragma unroll
        for (int i = tid; i < (D * D) / 4; i += 128) ws4[i] = w4[i];
    }
    for (int i = tid; i < 128 * (D / 4); i += 128) {
        int r = i >> 4, q = i & 15;
        int row = n0 + r;
        float4 x = make_float4(0.f, 0.f, 0.f, 0.f);
        if (row < end) {
            x = __ldg((const float4*)(in + (size_t)row * D) + q);
            if (use_relu) {
                float4 b = __ldg((const float4*)bias + q);
                x.x = fmaxf(x.x + b.x, 0.f); x.y = fmaxf(x.y + b.y, 0.f);
                x.z = fmaxf(x.z + b.z, 0.f); x.w = fmaxf(x.w + b.w, 0.f);
            }
            if (use_deg) {
                float di = __ldg(&g_dinv[row]);
                x.x *= di; x.y *= di; x.z *= di; x.w *= di;
            }
        }
        *(float4*)&Xs[r][q * 4] = x;
    }
    __syncthreads();

    const int rb = tid >> 2;          // rows rb, rb+32, rb+64, rb+96
    const int cq = (tid & 3) * 4;     // column chunk base within each 16-col group
    uint64_t acc0[8], acc1[8], acc2[8], acc3[8];
    #pragma unroll
    for (int i = 0; i < 8; i++) { acc0[i]=0ULL; acc1[i]=0ULL; acc2[i]=0ULL; acc3[i]=0ULL; }

    #pragma unroll 8
    for (int k = 0; k < D; k++) {
        uint64_t x0 = pack2(Xs[rb][k]);
        uint64_t x1 = pack2(Xs[rb + 32][k]);
        uint64_t x2 = pack2(Xs[rb + 64][k]);
        uint64_t x3 = pack2(Xs[rb + 96][k]);
        #pragma unroll
        for (int j = 0; j < 4; j++) {
            ulonglong2 w = *(const ulonglong2*)&Ws[k][j * 16 + cq];
            FMA2(acc0[2*j],   x0, w.x); FMA2(acc0[2*j+1], x0, w.y);
            FMA2(acc1[2*j],   x1, w.x); FMA2(acc1[2*j+1], x1, w.y);
            FMA2(acc2[2*j],   x2, w.x); FMA2(acc2[2*j+1], x2, w.y);
            FMA2(acc3[2*j],   x3, w.x); FMA2(acc3[2*j+1], x3, w.y);
        }
    }

    #pragma unroll
    for (int rr = 0; rr < 4; rr++) {
        int row = n0 + rb + rr * 32;
        if (row >= end) break;
        const uint64_t* acc = (rr == 0) ? acc0 : (rr == 1) ? acc1 : (rr == 2) ? acc2 : acc3;
        float* o = t_out + (size_t)row * D;
        #pragma unroll
        for (int j = 0; j < 4; j++)
            *(float4*)(o + j * 16 + cq) = make_float4(
                lo32(acc[2*j]),   hi32(acc[2*j]),
                lo32(acc[2*j+1]), hi32(acc[2*j+1]));
    }
}

// ---------------- gather core over ELL row, 8-edge batches (MLP=8) ---------------------
template <int APPLY_DEG>
__device__ __forceinline__ float4 agg_node(const float* __restrict__ t_in,
                                           int node, int lane) {
    int n = __ldg(&g_cnt[node]);
    n = (n < ELL_W) ? n : ELL_W;
    const int* lst = g_ell + (size_t)node * ELL_W;
    float4 acc = make_float4(0.f, 0.f, 0.f, 0.f);
    int e = 0;
    for (; e + 8 <= n; e += 8) {
        int s[8];
        #pragma unroll
        for (int i = 0; i < 8; i++) s[i] = __ldg(&lst[e + i]);
        float di[8];
        if (APPLY_DEG) {
            #pragma unroll
            for (int i = 0; i < 8; i++) di[i] = __ldg(&g_dinv[s[i]]);
        }
        float4 v[8];
        #pragma unroll
        for (int i = 0; i < 8; i++)
            v[i] = __ldg((const float4*)(t_in + (size_t)s[i] * D) + lane);
        #pragma unroll
        for (int i = 0; i < 8; i++) {
            float m = APPLY_DEG ? di[i] : 1.0f;
            acc.x += m * v[i].x; acc.y += m * v[i].y;
            acc.z += m * v[i].z; acc.w += m * v[i].w;
        }
    }
    for (; e < n; e++) {
        int s = __ldg(&lst[e]);
        float m = APPLY_DEG ? __ldg(&g_dinv[s]) : 1.0f;
        float4 v = __ldg((const float4*)(t_in + (size_t)s * D) + lane);
        acc.x += m * v.x; acc.y += m * v.y; acc.z += m * v.z; acc.w += m * v.w;
    }
    return acc;
}

// ---------------- aggregate over node range [base, base + 16*gridDim) ------------------
// layer 0 variant applies per-edge dinv[src] (deg commuted out of gemm0).
__global__ __launch_bounds__(256) void gcn_aggregate_deg(const float* __restrict__ t_in,
                                                         int base)
{
    int node = base + blockIdx.x * 16 + (threadIdx.x >> 4);
    int lane = threadIdx.x & 15;
    if (node >= N_NODES) return;
    float4 acc = agg_node<1>(t_in, node, lane);
    *((float4*)(g_agg + (size_t)node * D) + lane) = acc;
}

__global__ __launch_bounds__(256) void gcn_aggregate(const float* __restrict__ t_in,
                                                     int base)
{
    int node = base + blockIdx.x * 16 + (threadIdx.x >> 4);
    int lane = threadIdx.x & 15;
    if (node >= N_NODES) return;
    float4 acc = agg_node<0>(t_in, node, lane);
    *((float4*)(g_agg + (size_t)node * D) + lane) = acc;
}

// ---------------- aggregate final: +b2, write out, fused column sums -------------------
__global__ __launch_bounds__(256) void gcn_aggregate_final(
    const float* __restrict__ t_in, const float* __restrict__ b2,
    float* __restrict__ out)
{
    int node = blockIdx.x * 16 + (threadIdx.x >> 4);
    int lane = threadIdx.x & 15;

    float4 acc = agg_node<0>(t_in, node, lane);
    float4 bb  = __ldg((const float4*)b2 + lane);
    acc.x += bb.x; acc.y += bb.y; acc.z += bb.z; acc.w += bb.w;
    *((float4*)(out + (size_t)node * D) + lane) = acc;

    __shared__ float4 sdata[256];
    sdata[threadIdx.x] = acc;
    __syncthreads();
    #pragma unroll
    for (int off = 128; off >= 16; off >>= 1) {
        if (threadIdx.x < off) {
            float4 o = sdata[threadIdx.x + off];
            sdata[threadIdx.x].x += o.x; sdata[threadIdx.x].y += o.y;
            sdata[threadIdx.x].z += o.z; sdata[threadIdx.x].w += o.w;
        }
        __syncthreads();
    }
    if (threadIdx.x < 16) {
        float4 s = sdata[threadIdx.x];
        atomicAdd(&g_msum[threadIdx.x * 4 + 0], s.x);
        atomicAdd(&g_msum[threadIdx.x * 4 + 1], s.y);
        atomicAdd(&g_msum[threadIdx.x * 4 + 2], s.z);
        atomicAdd(&g_msum[threadIdx.x * 4 + 3], s.w);
    }
}

__global__ void gcn_mean_write(float* __restrict__ out) {
    int j = threadIdx.x;
    if (j < D) out[(size_t)N_NODES * D + j] = g_msum[j] / (float)N_NODES;
}

// ---------------- launch -----------------------------------------------------------------
extern "C" void kernel_launch(void* const* d_in, const int* in_sizes, int n_in,
                              void* d_out, int out_size)
{
    const float* features = (const float*)d_in[0];
    const void*  src      = d_in[1];
    const void*  dst      = d_in[2];
    const float* W0 = (const float*)d_in[3];
    const float* b0 = (const float*)d_in[4];
    const float* W1 = (const float*)d_in[5];
    const float* b1 = (const float*)d_in[6];
    const float* W2 = (const float*)d_in[7];
    const float* b2 = (const float*)d_in[8];
    float* out = (float*)d_out;

    const int threads     = 256;
    const int blocks_quad = (N_EDGES / 4 + threads - 1) / threads;  // 1563
    const int gemm_full   = (N_NODES + 127) / 128;                  // 782
    const int gemm_half   = (NH + 127) / 128;                       // 391
    const int agg_full    = N_NODES / 16;                           // 6250
    const int agg_half    = NH / 16;                                // 3125
    const int blocks_nodes = (N_NODES + threads - 1) / threads;     // 391

    // scratch buffer addresses (symbol lookup only — no allocation)
    float *t0, *t1, *agg;
    cudaGetSymbolAddress((void**)&t0, g_t0);
    cudaGetSymbolAddress((void**)&t1, g_t1);
    cudaGetSymbolAddress((void**)&agg, g_agg);

    // one-time side stream + events (host objects; created once, reused every call)
    static cudaStream_t s2 = nullptr;
    static cudaEvent_t evFork=nullptr, evJ0=nullptr, evA0A=nullptr,
                       evG1A=nullptr, evA1A=nullptr, evG2A=nullptr;
    static int infra_ready = 0;
    if (!infra_ready) {
        cudaStream_t tmp;
        if (cudaStreamCreateWithFlags(&tmp, cudaStreamNonBlocking) == cudaSuccess) {
            cudaEvent_t e[6]; bool ok = true;
            for (int i = 0; i < 6; i++)
                ok = ok && (cudaEventCreateWithFlags(&e[i], cudaEventDisableTiming) == cudaSuccess);
            if (ok) { s2 = tmp; evFork=e[0]; evJ0=e[1]; evA0A=e[2]; evG1A=e[3]; evA1A=e[4]; evG2A=e[5]; }
        }
        infra_ready = 1;
    }

    // zero scratch via memset engine
    void *p_cnt, *p_deg, *p_msum;
    cudaGetSymbolAddress(&p_cnt, g_cnt);
    cudaGetSymbolAddress(&p_deg, g_deg);
    cudaGetSymbolAddress(&p_msum, g_msum);
    cudaMemsetAsync(p_cnt, 0, N_NODES * sizeof(int));
    cudaMemsetAsync(p_deg, 0, N_NODES * sizeof(float));
    cudaMemsetAsync(p_msum, 0, D * sizeof(float));

    if (s2) {
        // ---- prefix: gemm0 (no deg dependency) || detect+build+deginv ----
        cudaEventRecord(evFork, 0);
        cudaStreamWaitEvent(s2, evFork, 0);
        gcn_gemm<<<gemm_full, 128, 0, s2>>>(features, W0, nullptr, t0, 0, 0, 0, N_NODES);
        cudaEventRecord(evJ0, s2);

        gcn_detect<<<1, 256>>>(src);
        gcn_build<<<blocks_quad, threads>>>(src, dst);
        gcn_deginv<<<blocks_nodes, threads>>>();
        cudaStreamWaitEvent(0, evJ0, 0);

        // ---- layer 0 agg / layer 1 gemm pipeline (reads t0, writes t1) ----
        gcn_aggregate_deg<<<agg_half, threads>>>(t0, 0);                     // A
        cudaEventRecord(evA0A, 0);
        cudaStreamWaitEvent(s2, evA0A, 0);
        gcn_gemm<<<gemm_half, 128, 0, s2>>>(agg, W1, b0, t1, 1, 1, 0, NH);   // gemm1 A
        cudaEventRecord(evG1A, s2);
        gcn_aggregate_deg<<<agg_half, threads>>>(t0, NH);                    // B (|| gemm1 A)
        gcn_gemm<<<gemm_half, 128>>>(agg, W1, b0, t1, 1, 1, NH, N_NODES);    // gemm1 B
        cudaStreamWaitEvent(0, evG1A, 0);

        // ---- layer 1 agg / layer 2 gemm pipeline (reads t1, writes t0) ----
        gcn_aggregate<<<agg_half, threads>>>(t1, 0);                         // A
        cudaEventRecord(evA1A, 0);
        cudaStreamWaitEvent(s2, evA1A, 0);
        gcn_gemm<<<gemm_half, 128, 0, s2>>>(agg, W2, b1, t0, 1, 1, 0, NH);   // gemm2 A
        cudaEventRecord(evG2A, s2);
        gcn_aggregate<<<agg_half, threads>>>(t1, NH);                        // B (|| gemm2 A)
        gcn_gemm<<<gemm_half, 128>>>(agg, W2, b1, t0, 1, 1, NH, N_NODES);    // gemm2 B
        cudaStreamWaitEvent(0, evG2A, 0);

        // ---- final aggregate (reads t0) + mean ----
        gcn_aggregate_final<<<agg_full, threads>>>(t0, b2, out);
        gcn_mean_write<<<1, 64>>>(out);
    } else {
        // serial fallback (identical math)
        gcn_detect<<<1, 256>>>(src);
        gcn_build<<<blocks_quad, threads>>>(src, dst);
        gcn_gemm<<<gemm_full, 128>>>(features, W0, nullptr, t0, 0, 0, 0, N_NODES);
        gcn_deginv<<<blocks_nodes, threads>>>();
        gcn_aggregate_deg<<<agg_full, threads>>>(t0, 0);
        gcn_gemm<<<gemm_full, 128>>>(agg, W1, b0, t1, 1, 1, 0, N_NODES);
        gcn_aggregate<<<agg_full, threads>>>(t1, 0);
        gcn_gemm<<<gemm_full, 128>>>(agg, W2, b1, t0, 1, 1, 0, N_NODES);
        gcn_aggregate_final<<<agg_full, threads>>>(t0, b2, out);
        gcn_mean_write<<<1, 64>>>(out);
    }
}